// round 16
// baseline (speedup 1.0000x reference)
#include <cuda_runtime.h>
#include <math.h>
#include <stdint.h>

#define B_L   192
#define NVAL  325
#define NPAD  352
#define D     256
#define DPOS  64
#define KPROJ 320
#define HEADS 8
#define EDIM  32
#define BH    (B_L*HEADS)      /* 1536 */
#define NH    4
#define NB    22
#define NC    (NH*NB)          /* 88 */
#define BKTS  16
#define NS    (NH*NPAD)        /* 1408 */
#define MROWS (B_L*NPAD)       /* 67584 */
#define MVAL  (B_L*NVAL)       /* 62400 */
#define GRIDM 488              /* ceil(62400/128) */

typedef unsigned long long u64;

__device__ __forceinline__ u64 pack2(float x, float y) {
    u64 r; asm("mov.b64 %0,{%1,%2};" : "=l"(r) : "f"(x), "f"(y)); return r;
}
__device__ __forceinline__ void unpack2(u64 v, float& x, float& y) {
    asm("mov.b64 {%0,%1},%2;" : "=f"(x), "=f"(y) : "l"(v));
}
__device__ __forceinline__ u64 fma2(u64 a, u64 b, u64 c) {
    u64 d; asm("fma.rn.f32x2 %0,%1,%2,%3;" : "=l"(d) : "l"(a), "l"(b), "l"(c)); return d;
}

// ---------------- scratch -------------------------------------------------------
__device__ __align__(16) float g_h    [MROWS*D];
__device__ __align__(16) float g_qk   [BH*NPAD*EDIM];
__device__ __align__(16) float g_v    [BH*NPAD*EDIM];
__device__ int   g_sticker[BH*NS];
__device__ __align__(16) float g_o    [BH*NH*NPAD*EDIM];
__device__ float g_lse  [BH*NH*NPAD];
__device__ __align__(16) float g_hcomb[MROWS*D];

// -------- 128x128 SGEMM over VALID rows, BK=8, 8x8/thread quadrants, FFMA2 -----
template<int MODE>
__global__ __launch_bounds__(256, 2)
void gemm_k(const float* __restrict__ P0, const float* __restrict__ P1,
            const float* __restrict__ W0, const float* __restrict__ W1,
            const float* __restrict__ bias, float* __restrict__ Cout)
{
    constexpr int BM = 128, BN = 128, BK = 8;
    constexpr int KDIM = (MODE == 0) ? KPROJ : 256;
    constexpr int NT   = KDIM / BK;
    constexpr int LDA  = BM + 4;

    __shared__ float As[2][BK][LDA];
    __shared__ float Bs[2][BK][BN];

    const int tid = threadIdx.x;
    const int bm  = blockIdx.x * BM;
    const int bn  = blockIdx.y * BN;

    const int arow  = tid >> 1;
    const int akoff = (tid & 1) * 4;
    const int bk    = tid >> 5;
    const int bcol  = (tid & 31) * 4;

    const int r = bm + arow;
    const bool validA = (r < MVAL);
    long baseA = 0, baseS = 0;
    if (MODE == 0) {
        baseA = (long)r * D;
        baseS = (long)r * DPOS;
    } else {
        int rr = validA ? r : 0;
        int b_l = rr / NVAL, n = rr - b_l * NVAL;
        baseA = ((long)b_l * NPAD + n) * D;
    }

    const float* Wp;
    int wbase;
    if (MODE == 1 && bn >= 256) { Wp = W1; wbase = bn - 256; }
    else                         { Wp = W0; wbase = bn; }

    float4 aReg, bReg;

    auto load_gmem = [&](int kt) {
        int kk = kt + akoff;
        if (MODE == 0) {
            if (!validA) aReg = make_float4(0.f, 0.f, 0.f, 0.f);
            else if (kk < D) aReg = *(const float4*)(P0 + baseA + kk);
            else             aReg = *(const float4*)(P1 + baseS + (kk - D));
        } else if (MODE == 1) {
            aReg = *(const float4*)(g_h + baseA + kk);
        } else {
            aReg = *(const float4*)(g_hcomb + baseA + kk);
        }
        bReg = *(const float4*)(Wp + (long)(kt + bk) * D + wbase + bcol);
    };
    auto store_smem = [&](int buf) {
        As[buf][akoff + 0][arow] = aReg.x;
        As[buf][akoff + 1][arow] = aReg.y;
        As[buf][akoff + 2][arow] = aReg.z;
        As[buf][akoff + 3][arow] = aReg.w;
        *(float4*)(&Bs[buf][bk][bcol]) = bReg;
    };

    const int ty = tid >> 4;
    const int tx = tid & 15;

    u64 acc2[2][2][4][2];
#pragma unroll
    for (int gi = 0; gi < 2; gi++)
#pragma unroll
        for (int gj = 0; gj < 2; gj++)
#pragma unroll
            for (int i = 0; i < 4; i++) {
                acc2[gi][gj][i][0] = 0ULL;
                acc2[gi][gj][i][1] = 0ULL;
            }

    load_gmem(0);
    store_smem(0);
    __syncthreads();

    int buf = 0;
    for (int t = 0; t < NT; ++t) {
        if (t + 1 < NT) load_gmem((t + 1) * BK);
#pragma unroll
        for (int k = 0; k < BK; k++) {
            float4 a0 = *(const float4*)(&As[buf][k][ty * 4]);
            float4 a1 = *(const float4*)(&As[buf][k][64 + ty * 4]);
            float4 b0 = *(const float4*)(&Bs[buf][k][tx * 4]);
            float4 b1 = *(const float4*)(&Bs[buf][k][64 + tx * 4]);
            u64 bp[2][2] = {{pack2(b0.x, b0.y), pack2(b0.z, b0.w)},
                            {pack2(b1.x, b1.y), pack2(b1.z, b1.w)}};
            float av[2][4] = {{a0.x, a0.y, a0.z, a0.w}, {a1.x, a1.y, a1.z, a1.w}};
#pragma unroll
            for (int gi = 0; gi < 2; gi++)
#pragma unroll
                for (int i = 0; i < 4; i++) {
                    u64 ap = pack2(av[gi][i], av[gi][i]);
#pragma unroll
                    for (int gj = 0; gj < 2; gj++) {
                        acc2[gi][gj][i][0] = fma2(ap, bp[gj][0], acc2[gi][gj][i][0]);
                        acc2[gi][gj][i][1] = fma2(ap, bp[gj][1], acc2[gi][gj][i][1]);
                    }
                }
        }
        if (t + 1 < NT) {
            store_smem(buf ^ 1);
            __syncthreads();
            buf ^= 1;
        }
    }

#pragma unroll
    for (int gi = 0; gi < 2; gi++)
#pragma unroll
    for (int i = 0; i < 4; i++) {
        int ro = bm + gi * 64 + ty * 4 + i;
        if (ro >= MVAL) continue;
#pragma unroll
        for (int gj = 0; gj < 2; gj++) {
            int cb = bn + gj * 64 + tx * 4;
            float c0, c1, c2, c3;
            unpack2(acc2[gi][gj][i][0], c0, c1);
            unpack2(acc2[gi][gj][i][1], c2, c3);

            if (MODE == 0) {
                int b_l = ro / NVAL, n = ro - b_l * NVAL;
                *(float4*)(g_h + ((long)b_l * NPAD + n) * D + cb) =
                    make_float4(c0 + bias[cb + 0], c1 + bias[cb + 1],
                                c2 + bias[cb + 2], c3 + bias[cb + 3]);
            } else if (MODE == 1) {
                int b_l = ro / NVAL, n = ro - b_l * NVAL;
                int cc = cb;
                float* dst;
                if (cc < D) { int head = cc >> 5; int e = cc & 31;
                    dst = g_qk + ((long)((b_l << 3) + head) * NPAD + n) * EDIM + e; }
                else { cc -= D; int head = cc >> 5; int e = cc & 31;
                    dst = g_v  + ((long)((b_l << 3) + head) * NPAD + n) * EDIM + e; }
                *(float4*)(dst) = make_float4(c0, c1, c2, c3);
            } else {
                *(float4*)(Cout + (long)ro * D + cb) =
                    make_float4(c0 + bias[cb + 0], c1 + bias[cb + 1],
                                c2 + bias[cb + 2], c3 + bias[cb + 3]);
            }
        }
    }
}

// ------- fused: pad-zero + hash (bit-identical chains) + stable counting sort ----
__global__ __launch_bounds__(256)
void hashsort_kernel(const float* __restrict__ rot)
{
    const int bh  = blockIdx.x;
    const int tid = threadIdx.x;

    __shared__ u64 srot2[EDIM][NH][6];
    __shared__ unsigned short hist[128][89];
    __shared__ int sbuck[NS];
    __shared__ int base[NC];
    __shared__ int tot[NC];

    // vectorized pad-row zero fill (16B aligned: offsets are multiples of 4 floats)
    for (int i = tid; i < (NPAD - NVAL) * (EDIM / 4); i += 256) {
        int pi = i >> 3, e4 = (i & 7) * 4;
        long off = ((long)bh * NPAD + NVAL + pi) * EDIM + e4;
        float4 z = make_float4(0.f, 0.f, 0.f, 0.f);
        *(float4*)(g_qk + off) = z;
        *(float4*)(g_v + off)  = z;
    }
    for (int i = tid; i < EDIM * NH * 6; i += 256) {
        int e  = i / (NH * 6);
        int h  = (i / 6) % NH;
        int rr = i % 6;
        int r0 = 2 * rr, r1 = 2 * rr + 1;
        float xv = (r0 < NB / 2) ? rot[(e * NH + h) * (NB / 2) + r0] : 0.f;
        float yv = (r1 < NB / 2) ? rot[(e * NH + h) * (NB / 2) + r1] : 0.f;
        srot2[e][h][rr] = pack2(xv, yv);
    }
    __syncthreads();

    for (int n = tid; n < NPAD; n += 256) {
        if (n >= NVAL) {
            for (int h = 0; h < NH; h++) sbuck[h * NPAD + n] = h * NB;
            continue;
        }
        float q[EDIM];
        const float* qp = &g_qk[(long)(bh * NPAD + n) * EDIM];
#pragma unroll
        for (int e = 0; e < EDIM; e += 4) {
            float4 t = *(const float4*)(qp + e);
            q[e] = t.x; q[e + 1] = t.y; q[e + 2] = t.z; q[e + 3] = t.w;
        }
        for (int h = 0; h < NH; h++) {
            u64 s2[6];
#pragma unroll
            for (int rr = 0; rr < 6; rr++) s2[rr] = 0ULL;
#pragma unroll
            for (int e = 0; e < EDIM; e++) {
                u64 qq = pack2(q[e], q[e]);
#pragma unroll
                for (int rr = 0; rr < 6; rr++)
                    s2[rr] = fma2(qq, srot2[e][h][rr], s2[rr]);
            }
            float rv[12];
#pragma unroll
            for (int rr = 0; rr < 6; rr++) unpack2(s2[rr], rv[2 * rr], rv[2 * rr + 1]);

            float best = rv[0];
            int bi = 0;
#pragma unroll
            for (int r = 1; r < NB / 2; r++)
                if (rv[r] > best) { best = rv[r]; bi = r; }
#pragma unroll
            for (int r = 0; r < NB / 2; r++)
                if (-rv[r] > best) { best = -rv[r]; bi = r + NB / 2; }
            sbuck[h * NPAD + n] = bi + h * NB;
        }
    }
    __syncthreads();

    if (tid < 128)
        for (int b = 0; b < NC; b++) hist[tid][b] = 0;
    __syncthreads();

    if (tid < 128) {
#pragma unroll
        for (int k = 0; k < NS / 128; k++) {
            int i = tid * (NS / 128) + k;
            hist[tid][sbuck[i]]++;
        }
    }
    __syncthreads();

    if (tid < NC) {
        int s = 0;
        for (int t = 0; t < 128; t++) s += hist[t][tid];
        tot[tid] = s;
    }
    __syncthreads();
    if (tid == 0) {
        int run = 0;
        for (int b = 0; b < NC; b++) { base[b] = run; run += tot[b]; }
    }
    __syncthreads();
    if (tid < NC) {
        int run = base[tid];
        for (int t = 0; t < 128; t++) {
            int c = hist[t][tid];
            hist[t][tid] = (unsigned short)run;
            run += c;
        }
    }
    __syncthreads();

    if (tid < 128) {
#pragma unroll
        for (int k = 0; k < NS / 128; k++) {
            int i = tid * (NS / 128) + k;
            int b = sbuck[i];
            int pos = hist[tid][b]++;
            g_sticker[bh * NS + pos] = i;
        }
    }
}

// ------- attention: 4 warps per chunk; K/V register-resident; 4-query ILP -------
// Vectorized staging (LDG.128 + STS.64); all arithmetic chains identical to R15.
__global__ __launch_bounds__(128)
void attn_kernel()
{
    const int c  = blockIdx.x;
    const int bh = blockIdx.y;

    __shared__ __align__(8) float kq[32][34];
    __shared__ __align__(8) float vv[32][34];
    __shared__ float rn[32];
    __shared__ int   nn[32];
    __shared__ int   hh[32];
    __shared__ __align__(8) u64 p2[4][4][16];   // [warp][query][pair]

    const int tid  = threadIdx.x;
    const int warp = tid >> 5;
    const int lane = tid & 31;

    if (tid < 32) {
        int cj   = (tid < BKTS) ? c : (c + NC - 1) % NC;
        int slot = cj * BKTS + (tid & (BKTS - 1));
        int item = g_sticker[bh * NS + slot];
        int n    = item % NPAD;
        nn[tid] = n;
        hh[tid] = item / NPAD;
    }
    __syncthreads();

    // vectorized staging: 512 float4 transfers (kq: 256, vv: 256), 4 per thread
#pragma unroll
    for (int it = 0; it < 4; it++) {
        int idx = it * 128 + tid;
        int arr = idx >> 8;          // 0 = kq, 1 = vv
        int rem = idx & 255;
        int row = rem >> 3;
        int e4  = (rem & 7) * 4;
        long off = (long)(bh * NPAD + nn[row]) * EDIM + e4;
        float4 t = arr ? *(const float4*)(g_v + off) : *(const float4*)(g_qk + off);
        float* dst = arr ? &vv[row][e4] : &kq[row][e4];
        *(float2*)(dst)     = make_float2(t.x, t.y);
        *(float2*)(dst + 2) = make_float2(t.z, t.w);
    }
    __syncthreads();

    if (tid < 32) {
        u64 s2 = 0ULL;
#pragma unroll
        for (int e2 = 0; e2 < EDIM / 2; e2++) {
            u64 kk = *(const u64*)(&kq[tid][2 * e2]);
            s2 = fma2(kk, kk, s2);
        }
        float sa, sb; unpack2(s2, sa, sb);
        float s = sqrtf(sa + sb);
        rn[tid] = 1.0f / fmaxf(s, 1e-12f);
    }
    __syncthreads();

    const int nn_own = nn[lane];
    const float rn_own = rn[lane];

    u64 kreg[16];
#pragma unroll
    for (int e2 = 0; e2 < 16; e2++)
        kreg[e2] = *(const u64*)(&kq[lane][2 * e2]);

    u64 vreg[16];
#pragma unroll
    for (int jj = 0; jj < 16; jj++)
        vreg[jj] = pack2(vv[jj][lane], vv[jj + 16][lane]);

    // ---- phase 1: 4 interleaved dots ----
    u64 d2[4] = {0ULL, 0ULL, 0ULL, 0ULL};
#pragma unroll
    for (int e2 = 0; e2 < 16; e2++) {
        u64 kk = kreg[e2];
#pragma unroll
        for (int qq = 0; qq < 4; qq++) {
            u64 qa = *(const u64*)(&kq[warp * 4 + qq][2 * e2]);   // broadcast
            d2[qq] = fma2(qa, kk, d2[qq]);
        }
    }

    float d[4];
    int nn_q[4];
#pragma unroll
    for (int qq = 0; qq < 4; qq++) {
        nn_q[qq] = nn[warp * 4 + qq];
        float dl, dh; unpack2(d2[qq], dl, dh);
        d[qq] = (dl + dh) * rn_own * 0.17677669529663687f;
        if (nn_q[qq] == nn_own) d[qq] = -50000.0f;
    }

    // ---- phase 2: 4 interleaved softmax reductions ----
    float m[4] = {d[0], d[1], d[2], d[3]};
#pragma unroll
    for (int o = 16; o > 0; o >>= 1)
#pragma unroll
        for (int qq = 0; qq < 4; qq++)
            m[qq] = fmaxf(m[qq], __shfl_xor_sync(0xffffffffu, m[qq], o));

    float ex[4], sum[4];
#pragma unroll
    for (int qq = 0; qq < 4; qq++) { ex[qq] = expf(d[qq] - m[qq]); sum[qq] = ex[qq]; }
#pragma unroll
    for (int o = 16; o > 0; o >>= 1)
#pragma unroll
        for (int qq = 0; qq < 4; qq++)
            sum[qq] += __shfl_xor_sync(0xffffffffu, sum[qq], o);

    float lse[4], p[4];
#pragma unroll
    for (int qq = 0; qq < 4; qq++) {
        lse[qq] = m[qq] + logf(sum[qq]);
        p[qq]   = ex[qq] / sum[qq];
    }

#pragma unroll
    for (int qq = 0; qq < 4; qq++) {
        float phi = __shfl_xor_sync(0xffffffffu, p[qq], 16);
        if (lane < 16) p2[warp][qq][lane] = pack2(p[qq], phi);
    }
    __syncwarp();

    // ---- phase 3: 4 interleaved PV chains ----
    u64 acc2v[4] = {0ULL, 0ULL, 0ULL, 0ULL};
#pragma unroll
    for (int jj = 0; jj < 16; jj++) {
        u64 vj = vreg[jj];
#pragma unroll
        for (int qq = 0; qq < 4; qq++)
            acc2v[qq] = fma2(p2[warp][qq][jj], vj, acc2v[qq]);
    }

#pragma unroll
    for (int qq = 0; qq < 4; qq++) {
        float aA, aB; unpack2(acc2v[qq], aA, aB);
        float accv = aA + aB;
        int h_i = hh[warp * 4 + qq];
        g_o[((long)(bh * NH + h_i) * NPAD + nn_q[qq]) * EDIM + lane] = accv;
        if (lane == 0) g_lse[(bh * NH + h_i) * NPAD + nn_q[qq]] = lse[qq];
    }
}

// ---------------- combine hashes (valid rows only) -------------------------------
__global__ __launch_bounds__(256)
void combine_kernel()
{
    int gid  = blockIdx.x * blockDim.x + threadIdx.x;
    int wid  = gid >> 5;
    int lane = gid & 31;
    if (wid >= BH * NPAD) return;
    int bh = wid / NPAD;
    int n  = wid - bh * NPAD;
    if (n >= NVAL) return;

    float l0 = g_lse[(bh * NH + 0) * NPAD + n];
    float l1 = g_lse[(bh * NH + 1) * NPAD + n];
    float l2 = g_lse[(bh * NH + 2) * NPAD + n];
    float l3 = g_lse[(bh * NH + 3) * NPAD + n];
    float m = fmaxf(fmaxf(l0, l1), fmaxf(l2, l3));
    float e0 = expf(l0 - m), e1 = expf(l1 - m), e2 = expf(l2 - m), e3 = expf(l3 - m);
    float inv = 1.0f / (e0 + e1 + e2 + e3);

    float acc =
        e0 * inv * g_o[((long)(bh * NH + 0) * NPAD + n) * EDIM + lane] +
        e1 * inv * g_o[((long)(bh * NH + 1) * NPAD + n) * EDIM + lane] +
        e2 * inv * g_o[((long)(bh * NH + 2) * NPAD + n) * EDIM + lane] +
        e3 * inv * g_o[((long)(bh * NH + 3) * NPAD + n) * EDIM + lane];

    int b_l = bh >> 3, head = bh & 7;
    g_hcomb[(long)(b_l * NPAD + n) * D + head * EDIM + lane] = acc;
}

// ---------------- launch --------------------------------------------------------
extern "C" void kernel_launch(void* const* d_in, const int* in_sizes, int n_in,
                              void* d_out, int out_size)
{
    const float* x      = (const float*)d_in[0];
    const float* ste    = (const float*)d_in[1];
    const float* w_proj = (const float*)d_in[2];
    const float* b_proj = (const float*)d_in[3];
    const float* w_qk   = (const float*)d_in[4];
    const float* w_v    = (const float*)d_in[5];
    const float* w_out  = (const float*)d_in[6];
    const float* b_out  = (const float*)d_in[7];
    const float* rots   = (const float*)d_in[8];
    float* out = (float*)d_out;

    // attn_kernel stays the profiler's fixed 4th-launch slot
    gemm_k<0><<<dim3(GRIDM, 2), 256>>>(x, ste, w_proj, nullptr, b_proj, nullptr);
    gemm_k<1><<<dim3(GRIDM, 4), 256>>>(nullptr, nullptr, w_qk, w_v, nullptr, nullptr);
    hashsort_kernel<<<BH, 256>>>(rots);
    attn_kernel<<<dim3(NC, BH), 128>>>();
    combine_kernel<<<(BH * NPAD * 32 + 255) / 256, 256>>>();
    gemm_k<2><<<dim3(GRIDM, 2), 256>>>(nullptr, nullptr, w_out, nullptr, b_out, out);
}

// round 17
// speedup vs baseline: 1.4407x; 1.4407x over previous
#include <cuda_runtime.h>
#include <math.h>
#include <stdint.h>

#define B_L   192
#define NVAL  325
#define NPAD  352
#define D     256
#define DPOS  64
#define KPROJ 320
#define HEADS 8
#define EDIM  32
#define BH    (B_L*HEADS)      /* 1536 */
#define NH    4
#define NB    22
#define NC    (NH*NB)          /* 88 */
#define BKTS  16
#define NS    (NH*NPAD)        /* 1408 */
#define MROWS (B_L*NPAD)       /* 67584 */
#define MVAL  (B_L*NVAL)       /* 62400 */
#define GRIDM 488              /* ceil(62400/128) */

typedef unsigned long long u64;

__device__ __forceinline__ u64 pack2(float x, float y) {
    u64 r; asm("mov.b64 %0,{%1,%2};" : "=l"(r) : "f"(x), "f"(y)); return r;
}
__device__ __forceinline__ void unpack2(u64 v, float& x, float& y) {
    asm("mov.b64 {%0,%1},%2;" : "=f"(x), "=f"(y) : "l"(v));
}
__device__ __forceinline__ u64 fma2(u64 a, u64 b, u64 c) {
    u64 d; asm("fma.rn.f32x2 %0,%1,%2,%3;" : "=l"(d) : "l"(a), "l"(b), "l"(c)); return d;
}

// ---------------- scratch -------------------------------------------------------
__device__ __align__(16) float g_h    [MROWS*D];
__device__ __align__(16) float g_qk   [BH*NPAD*EDIM];
__device__ __align__(16) float g_v    [BH*NPAD*EDIM];
__device__ int   g_sticker[BH*NS];
__device__ __align__(16) float g_o    [BH*NH*NPAD*EDIM];
__device__ float g_lse  [BH*NH*NPAD];
__device__ __align__(16) float g_hcomb[MROWS*D];

// -------- 128x128 SGEMM over VALID rows, BK=8, 8x8/thread quadrants, FFMA2 -----
template<int MODE>
__global__ __launch_bounds__(256, 2)
void gemm_k(const float* __restrict__ P0, const float* __restrict__ P1,
            const float* __restrict__ W0, const float* __restrict__ W1,
            const float* __restrict__ bias, float* __restrict__ Cout)
{
    constexpr int BM = 128, BN = 128, BK = 8;
    constexpr int KDIM = (MODE == 0) ? KPROJ : 256;
    constexpr int NT   = KDIM / BK;
    constexpr int LDA  = BM + 4;

    __shared__ float As[2][BK][LDA];
    __shared__ float Bs[2][BK][BN];

    const int tid = threadIdx.x;
    const int bm  = blockIdx.x * BM;
    const int bn  = blockIdx.y * BN;

    const int arow  = tid >> 1;
    const int akoff = (tid & 1) * 4;
    const int bk    = tid >> 5;
    const int bcol  = (tid & 31) * 4;

    const int r = bm + arow;
    const bool validA = (r < MVAL);
    long baseA = 0, baseS = 0;
    if (MODE == 0) {
        baseA = (long)r * D;
        baseS = (long)r * DPOS;
    } else {
        int rr = validA ? r : 0;
        int b_l = rr / NVAL, n = rr - b_l * NVAL;
        baseA = ((long)b_l * NPAD + n) * D;
    }

    const float* Wp;
    int wbase;
    if (MODE == 1 && bn >= 256) { Wp = W1; wbase = bn - 256; }
    else                         { Wp = W0; wbase = bn; }

    float4 aReg, bReg;

    auto load_gmem = [&](int kt) {
        int kk = kt + akoff;
        if (MODE == 0) {
            if (!validA) aReg = make_float4(0.f, 0.f, 0.f, 0.f);
            else if (kk < D) aReg = *(const float4*)(P0 + baseA + kk);
            else             aReg = *(const float4*)(P1 + baseS + (kk - D));
        } else if (MODE == 1) {
            aReg = *(const float4*)(g_h + baseA + kk);
        } else {
            aReg = *(const float4*)(g_hcomb + baseA + kk);
        }
        bReg = *(const float4*)(Wp + (long)(kt + bk) * D + wbase + bcol);
    };
    auto store_smem = [&](int buf) {
        As[buf][akoff + 0][arow] = aReg.x;
        As[buf][akoff + 1][arow] = aReg.y;
        As[buf][akoff + 2][arow] = aReg.z;
        As[buf][akoff + 3][arow] = aReg.w;
        *(float4*)(&Bs[buf][bk][bcol]) = bReg;
    };

    const int ty = tid >> 4;
    const int tx = tid & 15;

    u64 acc2[2][2][4][2];
#pragma unroll
    for (int gi = 0; gi < 2; gi++)
#pragma unroll
        for (int gj = 0; gj < 2; gj++)
#pragma unroll
            for (int i = 0; i < 4; i++) {
                acc2[gi][gj][i][0] = 0ULL;
                acc2[gi][gj][i][1] = 0ULL;
            }

    load_gmem(0);
    store_smem(0);
    __syncthreads();

    int buf = 0;
    for (int t = 0; t < NT; ++t) {
        if (t + 1 < NT) load_gmem((t + 1) * BK);
#pragma unroll
        for (int k = 0; k < BK; k++) {
            float4 a0 = *(const float4*)(&As[buf][k][ty * 4]);
            float4 a1 = *(const float4*)(&As[buf][k][64 + ty * 4]);
            float4 b0 = *(const float4*)(&Bs[buf][k][tx * 4]);
            float4 b1 = *(const float4*)(&Bs[buf][k][64 + tx * 4]);
            u64 bp[2][2] = {{pack2(b0.x, b0.y), pack2(b0.z, b0.w)},
                            {pack2(b1.x, b1.y), pack2(b1.z, b1.w)}};
            float av[2][4] = {{a0.x, a0.y, a0.z, a0.w}, {a1.x, a1.y, a1.z, a1.w}};
#pragma unroll
            for (int gi = 0; gi < 2; gi++)
#pragma unroll
                for (int i = 0; i < 4; i++) {
                    u64 ap = pack2(av[gi][i], av[gi][i]);
#pragma unroll
                    for (int gj = 0; gj < 2; gj++) {
                        acc2[gi][gj][i][0] = fma2(ap, bp[gj][0], acc2[gi][gj][i][0]);
                        acc2[gi][gj][i][1] = fma2(ap, bp[gj][1], acc2[gi][gj][i][1]);
                    }
                }
        }
        if (t + 1 < NT) {
            store_smem(buf ^ 1);
            __syncthreads();
            buf ^= 1;
        }
    }

#pragma unroll
    for (int gi = 0; gi < 2; gi++)
#pragma unroll
    for (int i = 0; i < 4; i++) {
        int ro = bm + gi * 64 + ty * 4 + i;
        if (ro >= MVAL) continue;
#pragma unroll
        for (int gj = 0; gj < 2; gj++) {
            int cb = bn + gj * 64 + tx * 4;
            float c0, c1, c2, c3;
            unpack2(acc2[gi][gj][i][0], c0, c1);
            unpack2(acc2[gi][gj][i][1], c2, c3);

            if (MODE == 0) {
                int b_l = ro / NVAL, n = ro - b_l * NVAL;
                *(float4*)(g_h + ((long)b_l * NPAD + n) * D + cb) =
                    make_float4(c0 + bias[cb + 0], c1 + bias[cb + 1],
                                c2 + bias[cb + 2], c3 + bias[cb + 3]);
            } else if (MODE == 1) {
                int b_l = ro / NVAL, n = ro - b_l * NVAL;
                int cc = cb;
                float* dst;
                if (cc < D) { int head = cc >> 5; int e = cc & 31;
                    dst = g_qk + ((long)((b_l << 3) + head) * NPAD + n) * EDIM + e; }
                else { cc -= D; int head = cc >> 5; int e = cc & 31;
                    dst = g_v  + ((long)((b_l << 3) + head) * NPAD + n) * EDIM + e; }
                *(float4*)(dst) = make_float4(c0, c1, c2, c3);
            } else {
                *(float4*)(Cout + (long)ro * D + cb) =
                    make_float4(c0 + bias[cb + 0], c1 + bias[cb + 1],
                                c2 + bias[cb + 2], c3 + bias[cb + 3]);
            }
        }
    }
}

// ------- fused: pad-zero + hash (bit-identical chains) + stable counting sort ----
__global__ __launch_bounds__(256)
void hashsort_kernel(const float* __restrict__ rot)
{
    const int bh  = blockIdx.x;
    const int tid = threadIdx.x;

    __shared__ u64 srot2[EDIM][NH][6];
    __shared__ unsigned short hist[128][89];
    __shared__ int sbuck[NS];
    __shared__ int base[NC];
    __shared__ int tot[NC];

    // vectorized pad-row zero fill (16B aligned)
    for (int i = tid; i < (NPAD - NVAL) * (EDIM / 4); i += 256) {
        int pi = i >> 3, e4 = (i & 7) * 4;
        long off = ((long)bh * NPAD + NVAL + pi) * EDIM + e4;
        float4 z = make_float4(0.f, 0.f, 0.f, 0.f);
        *(float4*)(g_qk + off) = z;
        *(float4*)(g_v + off)  = z;
    }
    for (int i = tid; i < EDIM * NH * 6; i += 256) {
        int e  = i / (NH * 6);
        int h  = (i / 6) % NH;
        int rr = i % 6;
        int r0 = 2 * rr, r1 = 2 * rr + 1;
        float xv = (r0 < NB / 2) ? rot[(e * NH + h) * (NB / 2) + r0] : 0.f;
        float yv = (r1 < NB / 2) ? rot[(e * NH + h) * (NB / 2) + r1] : 0.f;
        srot2[e][h][rr] = pack2(xv, yv);
    }
    __syncthreads();

    for (int n = tid; n < NPAD; n += 256) {
        if (n >= NVAL) {
            for (int h = 0; h < NH; h++) sbuck[h * NPAD + n] = h * NB;
            continue;
        }
        float q[EDIM];
        const float* qp = &g_qk[(long)(bh * NPAD + n) * EDIM];
#pragma unroll
        for (int e = 0; e < EDIM; e += 4) {
            float4 t = *(const float4*)(qp + e);
            q[e] = t.x; q[e + 1] = t.y; q[e + 2] = t.z; q[e + 3] = t.w;
        }
        for (int h = 0; h < NH; h++) {
            u64 s2[6];
#pragma unroll
            for (int rr = 0; rr < 6; rr++) s2[rr] = 0ULL;
#pragma unroll
            for (int e = 0; e < EDIM; e++) {
                u64 qq = pack2(q[e], q[e]);
#pragma unroll
                for (int rr = 0; rr < 6; rr++)
                    s2[rr] = fma2(qq, srot2[e][h][rr], s2[rr]);
            }
            float rv[12];
#pragma unroll
            for (int rr = 0; rr < 6; rr++) unpack2(s2[rr], rv[2 * rr], rv[2 * rr + 1]);

            float best = rv[0];
            int bi = 0;
#pragma unroll
            for (int r = 1; r < NB / 2; r++)
                if (rv[r] > best) { best = rv[r]; bi = r; }
#pragma unroll
            for (int r = 0; r < NB / 2; r++)
                if (-rv[r] > best) { best = -rv[r]; bi = r + NB / 2; }
            sbuck[h * NPAD + n] = bi + h * NB;
        }
    }
    __syncthreads();

    if (tid < 128)
        for (int b = 0; b < NC; b++) hist[tid][b] = 0;
    __syncthreads();

    if (tid < 128) {
#pragma unroll
        for (int k = 0; k < NS / 128; k++) {
            int i = tid * (NS / 128) + k;
            hist[tid][sbuck[i]]++;
        }
    }
    __syncthreads();

    if (tid < NC) {
        int s = 0;
        for (int t = 0; t < 128; t++) s += hist[t][tid];
        tot[tid] = s;
    }
    __syncthreads();
    if (tid == 0) {
        int run = 0;
        for (int b = 0; b < NC; b++) { base[b] = run; run += tot[b]; }
    }
    __syncthreads();
    if (tid < NC) {
        int run = base[tid];
        for (int t = 0; t < 128; t++) {
            int c = hist[t][tid];
            hist[t][tid] = (unsigned short)run;
            run += c;
        }
    }
    __syncthreads();

    if (tid < 128) {
#pragma unroll
        for (int k = 0; k < NS / 128; k++) {
            int i = tid * (NS / 128) + k;
            int b = sbuck[i];
            int pos = hist[tid][b]++;
            g_sticker[bh * NS + pos] = i;
        }
    }
}

// ------- attention: 4 warps per chunk; K/V register-resident; 4-query ILP -------
// (exact R15 kernel — scalar warp=row staging; chains bit-identical, 3.450348e-07)
__global__ __launch_bounds__(128)
void attn_kernel()
{
    const int c  = blockIdx.x;
    const int bh = blockIdx.y;

    __shared__ __align__(8) float kq[32][34];
    __shared__ __align__(8) float vv[32][34];
    __shared__ float rn[32];
    __shared__ int   nn[32];
    __shared__ int   hh[32];
    __shared__ __align__(8) u64 p2[4][4][16];   // [warp][query][pair]

    const int tid  = threadIdx.x;
    const int warp = tid >> 5;
    const int lane = tid & 31;

    if (tid < 32) {
        int cj   = (tid < BKTS) ? c : (c + NC - 1) % NC;
        int slot = cj * BKTS + (tid & (BKTS - 1));
        int item = g_sticker[bh * NS + slot];
        int n    = item % NPAD;
        nn[tid] = n;
        hh[tid] = item / NPAD;
    }
    __syncthreads();

    for (int idx = tid; idx < 32 * EDIM; idx += 128) {
        int j = idx >> 5, e = idx & 31;
        long off = (long)(bh * NPAD + nn[j]) * EDIM + e;
        kq[j][e] = g_qk[off];
        vv[j][e] = g_v[off];
    }
    __syncthreads();

    if (tid < 32) {
        u64 s2 = 0ULL;
#pragma unroll
        for (int e2 = 0; e2 < EDIM / 2; e2++) {
            u64 kk = *(const u64*)(&kq[tid][2 * e2]);
            s2 = fma2(kk, kk, s2);
        }
        float sa, sb; unpack2(s2, sa, sb);
        float s = sqrtf(sa + sb);
        rn[tid] = 1.0f / fmaxf(s, 1e-12f);
    }
    __syncthreads();

    const int nn_own = nn[lane];
    const float rn_own = rn[lane];

    u64 kreg[16];
#pragma unroll
    for (int e2 = 0; e2 < 16; e2++)
        kreg[e2] = *(const u64*)(&kq[lane][2 * e2]);

    u64 vreg[16];
#pragma unroll
    for (int jj = 0; jj < 16; jj++)
        vreg[jj] = pack2(vv[jj][lane], vv[jj + 16][lane]);

    // ---- phase 1: 4 interleaved dots ----
    u64 d2[4] = {0ULL, 0ULL, 0ULL, 0ULL};
#pragma unroll
    for (int e2 = 0; e2 < 16; e2++) {
        u64 kk = kreg[e2];
#pragma unroll
        for (int qq = 0; qq < 4; qq++) {
            u64 qa = *(const u64*)(&kq[warp * 4 + qq][2 * e2]);   // broadcast
            d2[qq] = fma2(qa, kk, d2[qq]);
        }
    }

    float d[4];
    int nn_q[4];
#pragma unroll
    for (int qq = 0; qq < 4; qq++) {
        nn_q[qq] = nn[warp * 4 + qq];
        float dl, dh; unpack2(d2[qq], dl, dh);
        d[qq] = (dl + dh) * rn_own * 0.17677669529663687f;
        if (nn_q[qq] == nn_own) d[qq] = -50000.0f;
    }

    // ---- phase 2: 4 interleaved softmax reductions ----
    float m[4] = {d[0], d[1], d[2], d[3]};
#pragma unroll
    for (int o = 16; o > 0; o >>= 1)
#pragma unroll
        for (int qq = 0; qq < 4; qq++)
            m[qq] = fmaxf(m[qq], __shfl_xor_sync(0xffffffffu, m[qq], o));

    float ex[4], sum[4];
#pragma unroll
    for (int qq = 0; qq < 4; qq++) { ex[qq] = expf(d[qq] - m[qq]); sum[qq] = ex[qq]; }
#pragma unroll
    for (int o = 16; o > 0; o >>= 1)
#pragma unroll
        for (int qq = 0; qq < 4; qq++)
            sum[qq] += __shfl_xor_sync(0xffffffffu, sum[qq], o);

    float lse[4], p[4];
#pragma unroll
    for (int qq = 0; qq < 4; qq++) {
        lse[qq] = m[qq] + logf(sum[qq]);
        p[qq]   = ex[qq] / sum[qq];
    }

#pragma unroll
    for (int qq = 0; qq < 4; qq++) {
        float phi = __shfl_xor_sync(0xffffffffu, p[qq], 16);
        if (lane < 16) p2[warp][qq][lane] = pack2(p[qq], phi);
    }
    __syncwarp();

    // ---- phase 3: 4 interleaved PV chains ----
    u64 acc2v[4] = {0ULL, 0ULL, 0ULL, 0ULL};
#pragma unroll
    for (int jj = 0; jj < 16; jj++) {
        u64 vj = vreg[jj];
#pragma unroll
        for (int qq = 0; qq < 4; qq++)
            acc2v[qq] = fma2(p2[warp][qq][jj], vj, acc2v[qq]);
    }

#pragma unroll
    for (int qq = 0; qq < 4; qq++) {
        float aA, aB; unpack2(acc2v[qq], aA, aB);
        float accv = aA + aB;
        int h_i = hh[warp * 4 + qq];
        g_o[((long)(bh * NH + h_i) * NPAD + nn_q[qq]) * EDIM + lane] = accv;
        if (lane == 0) g_lse[(bh * NH + h_i) * NPAD + nn_q[qq]] = lse[qq];
    }
}

// ---------------- combine hashes (grid over valid rows only) ---------------------
__global__ __launch_bounds__(256)
void combine_kernel()
{
    int gid  = blockIdx.x * blockDim.x + threadIdx.x;
    int wid  = gid >> 5;
    int lane = gid & 31;
    if (wid >= BH * NVAL) return;
    int bh = wid / NVAL;
    int n  = wid - bh * NVAL;

    float l0 = g_lse[(bh * NH + 0) * NPAD + n];
    float l1 = g_lse[(bh * NH + 1) * NPAD + n];
    float l2 = g_lse[(bh * NH + 2) * NPAD + n];
    float l3 = g_lse[(bh * NH + 3) * NPAD + n];
    float m = fmaxf(fmaxf(l0, l1), fmaxf(l2, l3));
    float e0 = expf(l0 - m), e1 = expf(l1 - m), e2 = expf(l2 - m), e3 = expf(l3 - m);
    float inv = 1.0f / (e0 + e1 + e2 + e3);

    float acc =
        e0 * inv * g_o[((long)(bh * NH + 0) * NPAD + n) * EDIM + lane] +
        e1 * inv * g_o[((long)(bh * NH + 1) * NPAD + n) * EDIM + lane] +
        e2 * inv * g_o[((long)(bh * NH + 2) * NPAD + n) * EDIM + lane] +
        e3 * inv * g_o[((long)(bh * NH + 3) * NPAD + n) * EDIM + lane];

    int b_l = bh >> 3, head = bh & 7;
    g_hcomb[(long)(b_l * NPAD + n) * D + head * EDIM + lane] = acc;
}

// ---------------- launch --------------------------------------------------------
extern "C" void kernel_launch(void* const* d_in, const int* in_sizes, int n_in,
                              void* d_out, int out_size)
{
    const float* x      = (const float*)d_in[0];
    const float* ste    = (const float*)d_in[1];
    const float* w_proj = (const float*)d_in[2];
    const float* b_proj = (const float*)d_in[3];
    const float* w_qk   = (const float*)d_in[4];
    const float* w_v    = (const float*)d_in[5];
    const float* w_out  = (const float*)d_in[6];
    const float* b_out  = (const float*)d_in[7];
    const float* rots   = (const float*)d_in[8];
    float* out = (float*)d_out;

    // attn_kernel stays the profiler's fixed 4th-launch slot
    gemm_k<0><<<dim3(GRIDM, 2), 256>>>(x, ste, w_proj, nullptr, b_proj, nullptr);
    gemm_k<1><<<dim3(GRIDM, 4), 256>>>(nullptr, nullptr, w_qk, w_v, nullptr, nullptr);
    hashsort_kernel<<<BH, 256>>>(rots);
    attn_kernel<<<dim3(NC, BH), 128>>>();
    combine_kernel<<<(BH * NVAL * 32 + 255) / 256, 256>>>();
    gemm_k<2><<<dim3(GRIDM, 2), 256>>>(nullptr, nullptr, w_out, nullptr, b_out, out);
}